// round 1
// baseline (speedup 1.0000x reference)
#include <cuda_runtime.h>
#include <math.h>

// Problem constants
#define B_SZ   4096
#define N_AG   11
#define L_T    12
#define D_DIM  256
#define BN_ROWS (B_SZ * N_AG)      // 45056
#define K_MSG  512
#define K_FIN  1536

// ---------------- device scratch (no dynamic allocation allowed) ----------------
__device__ float g_M4[4 * 256];          // W_in @ W_pos[:256]
__device__ float g_biasT[12 * 256];      // per-timestep bias after W_pos
__device__ float g_Weff[48 * 256];       // folded input->fc2
__device__ float g_ceffp[12 * 256];      // partial const vectors
__device__ float g_ceff[256];
__device__ float g_G[48 * 256];          // folded input->ftraj matrix
__device__ float g_cb[11 * 256];         // per-agent bias (incl. eye@W_fc3)
__device__ float g_msgin[(size_t)BN_ROWS * 512];  // [ftraj | agg]
__device__ float g_hypin[(size_t)BN_ROWS * 512];  // [ftraj | hag]
__device__ float g_inter[(size_t)BN_ROWS * 256];  // ftraj_inter
__device__ float g_feat[(size_t)BN_ROWS * 64];    // feat_bs

// ---------------- precompute kernels (tiny, run every launch) ----------------
__global__ void pk1(const float* __restrict__ W_in, const float* __restrict__ b_in,
                    const float* __restrict__ W_pos, const float* __restrict__ b_pos) {
    __shared__ float pe[12 * 256];
    const int tid = threadIdx.x;   // 256 threads
    for (int idx = tid; idx < 12 * 256; idx += 256) {
        int t = idx >> 8, k = idx & 255;
        int i2 = k & ~1;
        float div = expf(-logf(10000.0f) * (float)i2 / 256.0f);
        float arg = (float)t * div;
        pe[idx] = (k & 1) ? cosf(arg) : sinf(arg);
    }
    __syncthreads();
    const int d = tid;
    float m[4] = {0.f, 0.f, 0.f, 0.f};
    float bb = 0.f;
    for (int k = 0; k < 256; k++) {
        float w = W_pos[k * 256 + d];
        #pragma unroll
        for (int r = 0; r < 4; r++) m[r] += W_in[r * 256 + k] * w;
        bb += b_in[k] * w;
    }
    #pragma unroll
    for (int r = 0; r < 4; r++) g_M4[r * 256 + d] = m[r];
    float acc[12];
    #pragma unroll
    for (int t = 0; t < 12; t++) acc[t] = bb + b_pos[d];
    for (int k = 0; k < 256; k++) {
        float w = W_pos[(256 + k) * 256 + d];
        #pragma unroll
        for (int t = 0; t < 12; t++) acc[t] += pe[t * 256 + k] * w;
    }
    #pragma unroll
    for (int t = 0; t < 12; t++) g_biasT[t * 256 + d] = acc[t];
}

__global__ void pk2(const float* __restrict__ W_fc2) {
    const int t = blockIdx.x, d = threadIdx.x;  // 12 blocks x 256
    float accW[4] = {0.f, 0.f, 0.f, 0.f};
    float accC = 0.f;
    for (int m = 0; m < 256; m++) {
        float w = W_fc2[(size_t)((t << 8) + m) * 256 + d];
        float bt = g_biasT[(t << 8) + m];
        #pragma unroll
        for (int r = 0; r < 4; r++) accW[r] += g_M4[r * 256 + m] * w;
        accC += bt * w;
    }
    #pragma unroll
    for (int r = 0; r < 4; r++) g_Weff[(t * 4 + r) * 256 + d] = accW[r];
    g_ceffp[t * 256 + d] = accC;
}

__global__ void pk3a(const float* __restrict__ b_fc2) {
    const int m = threadIdx.x;
    float s = b_fc2[m];
    #pragma unroll
    for (int t = 0; t < 12; t++) s += g_ceffp[t * 256 + m];
    g_ceff[m] = s;
}

__global__ void pk3b(const float* __restrict__ W_fc3, const float* __restrict__ b_fc3) {
    const int d = threadIdx.x;   // 49 blocks x 256
    if (blockIdx.x < 48) {
        const int i = blockIdx.x;
        float acc = 0.f;
        for (int m = 0; m < 256; m++) acc += g_Weff[i * 256 + m] * W_fc3[m * 256 + d];
        g_G[i * 256 + d] = acc;
    } else {
        float acc = b_fc3[d];
        for (int m = 0; m < 256; m++) acc += g_ceff[m] * W_fc3[m * 256 + d];
        #pragma unroll
        for (int n = 0; n < 11; n++) g_cb[n * 256 + d] = acc + W_fc3[(256 + n) * 256 + d];
    }
}

// ---------------- per-scene kernel: ftraj, corr/threshold, attn, agg, hag ----------------
__global__ void __launch_bounds__(256)
scene_kernel(const float* __restrict__ inputs) {
    __shared__ float in_s[11 * 48];
    __shared__ float ft[11 * 256];
    __shared__ float dot_s[121];
    __shared__ float corr_s[121];
    __shared__ float attn_s[121];
    __shared__ float arow_s[121];
    __shared__ float nrm[11];
    __shared__ float thr_s;

    const int b = blockIdx.x, tid = threadIdx.x;
    const float* ip = inputs + (size_t)b * 11 * 48;
    for (int i = tid; i < 528; i += 256) in_s[i] = ip[i];
    __syncthreads();

    // ftraj[n][tid] = cb[n][tid] + sum_k in48[n][k] * G[k][tid]
    float acc[11];
    #pragma unroll
    for (int n = 0; n < 11; n++) acc[n] = g_cb[n * 256 + tid];
    for (int k = 0; k < 48; k++) {
        float g = g_G[k * 256 + tid];
        #pragma unroll
        for (int n = 0; n < 11; n++) acc[n] += in_s[n * 48 + k] * g;
    }
    const size_t rowbase = (size_t)b * 11;
    #pragma unroll
    for (int n = 0; n < 11; n++) {
        ft[n * 256 + tid] = acc[n];
        g_msgin[(rowbase + n) * 512 + tid] = acc[n];
        g_hypin[(rowbase + n) * 512 + tid] = acc[n];
    }
    __syncthreads();

    // pairwise dots (warp-cooperative, upper triangle incl diag)
    const int warp = tid >> 5, lane = tid & 31;
    for (int p = warp; p < 121; p += 8) {
        int n = p / 11, m = p % 11;
        if (m < n) continue;
        float s = 0.f;
        #pragma unroll
        for (int i = 0; i < 8; i++)
            s += ft[n * 256 + lane + 32 * i] * ft[m * 256 + lane + 32 * i];
        #pragma unroll
        for (int o = 16; o > 0; o >>= 1) s += __shfl_down_sync(0xffffffffu, s, o);
        if (lane == 0) { dot_s[n * 11 + m] = s; dot_s[m * 11 + n] = s; }
    }
    __syncthreads();
    if (tid < 11) nrm[tid] = sqrtf(dot_s[tid * 11 + tid]);
    __syncthreads();
    if (tid < 121) {
        int n = tid / 11, m = tid % 11;
        corr_s[tid] = dot_s[tid] / (nrm[n] * nrm[m]);
    }
    __syncthreads();
    if (tid == 0) {
        float a = corr_s[0];
        for (int i = 1; i < 121; i++) a = fminf(a, corr_s[i]);
        float thr;
        if (a < 0.4f)                         thr = 0.4f;
        else if (a > 0.4f && a < 0.6f)        thr = a + 0.1f;
        else                                  thr = a + 0.03f;
        thr_s = thr;
    }
    __syncthreads();
    if (tid < 11) {
        const int n = tid;
        const float thr = thr_s;
        float rs = 0.f;
        #pragma unroll
        for (int m = 0; m < 11; m++) rs += (corr_s[n * 11 + m] >= thr) ? 1.0f : 0.0f;
        const float inv = 1.0f / fmaxf(rs, 1.0f);
        #pragma unroll
        for (int m = 0; m < 11; m++)
            arow_s[n * 11 + m] = (corr_s[n * 11 + m] >= thr) ? inv : 0.0f;
        // softmax(dot/16) row
        const float sc = 0.0625f;
        float mx = -1e30f;
        #pragma unroll
        for (int m = 0; m < 11; m++) mx = fmaxf(mx, dot_s[n * 11 + m] * sc);
        float e[11], se = 0.f;
        #pragma unroll
        for (int m = 0; m < 11; m++) { e[m] = expf(dot_s[n * 11 + m] * sc - mx); se += e[m]; }
        const float is = 1.0f / se;
        #pragma unroll
        for (int m = 0; m < 11; m++) attn_s[n * 11 + m] = e[m] * is;
    }
    __syncthreads();
    // agg / hag
    #pragma unroll
    for (int n = 0; n < 11; n++) {
        float a = 0.f, h = 0.f;
        #pragma unroll
        for (int m = 0; m < 11; m++) {
            float f = ft[m * 256 + tid];
            a += attn_s[n * 11 + m] * f;
            h += arow_s[n * 11 + m] * f;
        }
        g_msgin[(rowbase + n) * 512 + 256 + tid] = a;
        g_hypin[(rowbase + n) * 512 + 256 + tid] = h;
    }
}

// ---------------- GEMM 1: inter = relu(msgin @ W_msg + b_msg)  [45056,512]x[512,256] ----------------
__global__ void __launch_bounds__(256)
k_gemm_msg(const float* __restrict__ W, const float* __restrict__ bias) {
    __shared__ float As[2][8][128];
    __shared__ float Bs[2][8][128];
    const int tid = threadIdx.x;
    const int m0 = blockIdx.y * 128;
    const int n0 = blockIdx.x * 128;
    const int arow = tid >> 1, ac4 = (tid & 1) << 2;
    const int brow = tid >> 5, bc4 = (tid & 31) << 2;
    const float* Ap = g_msgin + (size_t)(m0 + arow) * 512 + ac4;
    const float* Wp = W + (size_t)brow * 256 + n0 + bc4;

    float4 ra = *(const float4*)Ap;
    float4 rb = *(const float4*)Wp;
    As[0][ac4 + 0][arow] = ra.x; As[0][ac4 + 1][arow] = ra.y;
    As[0][ac4 + 2][arow] = ra.z; As[0][ac4 + 3][arow] = ra.w;
    *(float4*)&Bs[0][brow][bc4] = rb;
    __syncthreads();

    float acc[8][8] = {};
    const int ty = tid >> 4, tx = tid & 15;
    #pragma unroll 2
    for (int kt = 0; kt < 64; kt++) {
        const int cur = kt & 1;
        if (kt < 63) {
            ra = *(const float4*)(Ap + (kt + 1) * 8);
            rb = *(const float4*)(Wp + (size_t)(kt + 1) * 2048);
        }
        #pragma unroll
        for (int k = 0; k < 8; k++) {
            float a[8], bv[8];
            *(float4*)&a[0]  = *(const float4*)&As[cur][k][ty * 8];
            *(float4*)&a[4]  = *(const float4*)&As[cur][k][ty * 8 + 4];
            *(float4*)&bv[0] = *(const float4*)&Bs[cur][k][tx * 8];
            *(float4*)&bv[4] = *(const float4*)&Bs[cur][k][tx * 8 + 4];
            #pragma unroll
            for (int i = 0; i < 8; i++)
                #pragma unroll
                for (int j = 0; j < 8; j++)
                    acc[i][j] += a[i] * bv[j];
        }
        if (kt < 63) {
            const int nxt = cur ^ 1;
            As[nxt][ac4 + 0][arow] = ra.x; As[nxt][ac4 + 1][arow] = ra.y;
            As[nxt][ac4 + 2][arow] = ra.z; As[nxt][ac4 + 3][arow] = ra.w;
            *(float4*)&Bs[nxt][brow][bc4] = rb;
            __syncthreads();
        }
    }
    float bn[8];
    #pragma unroll
    for (int j = 0; j < 8; j++) bn[j] = bias[n0 + tx * 8 + j];
    #pragma unroll
    for (int i = 0; i < 8; i++) {
        float4 o0 = make_float4(fmaxf(acc[i][0] + bn[0], 0.f), fmaxf(acc[i][1] + bn[1], 0.f),
                                fmaxf(acc[i][2] + bn[2], 0.f), fmaxf(acc[i][3] + bn[3], 0.f));
        float4 o1 = make_float4(fmaxf(acc[i][4] + bn[4], 0.f), fmaxf(acc[i][5] + bn[5], 0.f),
                                fmaxf(acc[i][6] + bn[6], 0.f), fmaxf(acc[i][7] + bn[7], 0.f));
        float* cp = g_inter + (size_t)(m0 + ty * 8 + i) * 256 + n0 + tx * 8;
        *(float4*)cp = o0;
        *(float4*)(cp + 4) = o1;
    }
}

// ---------------- GEMM 2: hyp = relu(hypin @ W_hyp + b_hyp); feat = hyp @ W_line (fused) ----------------
#define HYP_SMEM ((2*8*64 + 2*8*256 + 64*256) * 4)
__global__ void __launch_bounds__(256)
k_gemm_hyp(const float* __restrict__ W, const float* __restrict__ bias,
           const float* __restrict__ W_line) {
    extern __shared__ float sm[];
    float* As = sm;               // [2][8][64]
    float* Bs = sm + 1024;        // [2][8][256]
    float* Hs = sm + 1024 + 4096; // [64][256]
    const int tid = threadIdx.x;
    const int m0 = blockIdx.x * 64;
    const int arow = tid >> 1, ac4 = (tid & 1) << 2;
    const int f0r = tid >> 6, f0c = (tid & 63) << 2;
    const int f1r = 4 + (tid >> 6);
    const float* Ap = g_hypin + (size_t)(m0 + arow) * 512 + ac4;

    float4 ra = make_float4(0.f, 0.f, 0.f, 0.f), rb0, rb1;
    if (tid < 128) ra = *(const float4*)Ap;
    rb0 = *(const float4*)(W + (size_t)f0r * 256 + f0c);
    rb1 = *(const float4*)(W + (size_t)f1r * 256 + f0c);
    if (tid < 128) {
        As[(ac4 + 0) * 64 + arow] = ra.x; As[(ac4 + 1) * 64 + arow] = ra.y;
        As[(ac4 + 2) * 64 + arow] = ra.z; As[(ac4 + 3) * 64 + arow] = ra.w;
    }
    *(float4*)&Bs[f0r * 256 + f0c] = rb0;
    *(float4*)&Bs[f1r * 256 + f0c] = rb1;
    __syncthreads();

    float acc[8][8] = {};
    const int ty = tid >> 5, tx = tid & 31;
    #pragma unroll 2
    for (int kt = 0; kt < 64; kt++) {
        const int cur = kt & 1;
        if (kt < 63) {
            if (tid < 128) ra = *(const float4*)(Ap + (kt + 1) * 8);
            rb0 = *(const float4*)(W + (size_t)((kt + 1) * 8 + f0r) * 256 + f0c);
            rb1 = *(const float4*)(W + (size_t)((kt + 1) * 8 + f1r) * 256 + f0c);
        }
        const float* Asc = As + cur * 512;
        const float* Bsc = Bs + cur * 2048;
        #pragma unroll
        for (int k = 0; k < 8; k++) {
            float a[8], bv[8];
            *(float4*)&a[0]  = *(const float4*)&Asc[k * 64 + ty * 8];
            *(float4*)&a[4]  = *(const float4*)&Asc[k * 64 + ty * 8 + 4];
            *(float4*)&bv[0] = *(const float4*)&Bsc[k * 256 + tx * 8];
            *(float4*)&bv[4] = *(const float4*)&Bsc[k * 256 + tx * 8 + 4];
            #pragma unroll
            for (int i = 0; i < 8; i++)
                #pragma unroll
                for (int j = 0; j < 8; j++)
                    acc[i][j] += a[i] * bv[j];
        }
        if (kt < 63) {
            const int nxt = cur ^ 1;
            if (tid < 128) {
                As[nxt * 512 + (ac4 + 0) * 64 + arow] = ra.x;
                As[nxt * 512 + (ac4 + 1) * 64 + arow] = ra.y;
                As[nxt * 512 + (ac4 + 2) * 64 + arow] = ra.z;
                As[nxt * 512 + (ac4 + 3) * 64 + arow] = ra.w;
            }
            *(float4*)&Bs[nxt * 2048 + f0r * 256 + f0c] = rb0;
            *(float4*)&Bs[nxt * 2048 + f1r * 256 + f0c] = rb1;
            __syncthreads();
        }
    }
    // epilogue 1: hyp -> smem (never hits HBM)
    #pragma unroll
    for (int j = 0; j < 8; j++) {
        float bj = bias[tx * 8 + j];
        #pragma unroll
        for (int i = 0; i < 8; i++)
            Hs[(ty * 8 + i) * 256 + tx * 8 + j] = fmaxf(acc[i][j] + bj, 0.f);
    }
    __syncthreads();
    // epilogue 2: feat = Hs @ W_line  (64x256 @ 256x64)
    const int oc = tid & 63, og = tid >> 6;
    float o[16] = {};
    for (int k4 = 0; k4 < 64; k4++) {
        float w0 = W_line[(k4 * 4 + 0) * 64 + oc];
        float w1 = W_line[(k4 * 4 + 1) * 64 + oc];
        float w2 = W_line[(k4 * 4 + 2) * 64 + oc];
        float w3 = W_line[(k4 * 4 + 3) * 64 + oc];
        #pragma unroll
        for (int i = 0; i < 16; i++) {
            float4 h = *(const float4*)&Hs[(og * 16 + i) * 256 + k4 * 4];
            o[i] += h.x * w0 + h.y * w1 + h.z * w2 + h.w * w3;
        }
    }
    #pragma unroll
    for (int i = 0; i < 16; i++)
        g_feat[(size_t)(m0 + og * 16 + i) * 64 + oc] = o[i];
}

// ---------------- GEMM 3: h = relu([past|ftraj|inter|feat] @ W_out + b_out); out = h @ W_qz + b_qz ----------------
#define FIN_SMEM ((2048 + 2048 + 128*128) * 4)
__global__ void __launch_bounds__(256)
k_gemm_final(const float* __restrict__ past,
             const float* __restrict__ W_out, const float* __restrict__ b_out,
             const float* __restrict__ W_qz,  const float* __restrict__ b_qz,
             float* __restrict__ out) {
    extern __shared__ float sm[];
    float* As = sm;          // [2][8][128]
    float* Bs = sm + 2048;   // [2][8][128]
    float* Hs = sm + 4096;   // [128][128]
    const int tid = threadIdx.x;
    const int m0 = blockIdx.x * 128;
    const int arow = tid >> 1, ac4 = (tid & 1) << 2;
    const int brow = tid >> 5, bc4 = (tid & 31) << 2;
    const size_t grow = (size_t)(m0 + arow);

    auto aload = [&](int kt) -> float4 {
        const int k0 = kt * 8 + ac4;
        const float* p;
        if (k0 < 960)        p = past    + grow * 960 + k0;
        else if (k0 < 1216)  p = g_msgin + grow * 512 + (k0 - 960);
        else if (k0 < 1472)  p = g_inter + grow * 256 + (k0 - 1216);
        else                 p = g_feat  + grow * 64  + (k0 - 1472);
        return *(const float4*)p;
    };

    float4 ra = aload(0);
    float4 rb = *(const float4*)(W_out + (size_t)brow * 128 + bc4);
    As[(ac4 + 0) * 128 + arow] = ra.x; As[(ac4 + 1) * 128 + arow] = ra.y;
    As[(ac4 + 2) * 128 + arow] = ra.z; As[(ac4 + 3) * 128 + arow] = ra.w;
    *(float4*)&Bs[brow * 128 + bc4] = rb;
    __syncthreads();

    float acc[8][8] = {};
    const int ty = tid >> 4, tx = tid & 15;
    #pragma unroll 2
    for (int kt = 0; kt < 192; kt++) {
        const int cur = kt & 1;
        if (kt < 191) {
            ra = aload(kt + 1);
            rb = *(const float4*)(W_out + (size_t)((kt + 1) * 8 + brow) * 128 + bc4);
        }
        const float* Asc = As + cur * 1024;
        const float* Bsc = Bs + cur * 1024;
        #pragma unroll
        for (int k = 0; k < 8; k++) {
            float a[8], bv[8];
            *(float4*)&a[0]  = *(const float4*)&Asc[k * 128 + ty * 8];
            *(float4*)&a[4]  = *(const float4*)&Asc[k * 128 + ty * 8 + 4];
            *(float4*)&bv[0] = *(const float4*)&Bsc[k * 128 + tx * 8];
            *(float4*)&bv[4] = *(const float4*)&Bsc[k * 128 + tx * 8 + 4];
            #pragma unroll
            for (int i = 0; i < 8; i++)
                #pragma unroll
                for (int j = 0; j < 8; j++)
                    acc[i][j] += a[i] * bv[j];
        }
        if (kt < 191) {
            const int nxt = cur ^ 1;
            As[nxt * 1024 + (ac4 + 0) * 128 + arow] = ra.x;
            As[nxt * 1024 + (ac4 + 1) * 128 + arow] = ra.y;
            As[nxt * 1024 + (ac4 + 2) * 128 + arow] = ra.z;
            As[nxt * 1024 + (ac4 + 3) * 128 + arow] = ra.w;
            *(float4*)&Bs[nxt * 1024 + brow * 128 + bc4] = rb;
            __syncthreads();
        }
    }
    // epilogue 1: h = relu(acc + b_out) -> Hs
    #pragma unroll
    for (int j = 0; j < 8; j++) {
        float bj = b_out[tx * 8 + j];
        #pragma unroll
        for (int i = 0; i < 8; i++)
            Hs[(ty * 8 + i) * 128 + tx * 8 + j] = fmaxf(acc[i][j] + bj, 0.f);
    }
    __syncthreads();
    // epilogue 2: out = Hs @ W_qz + b_qz  (128x128 @ 128x64)
    const int oc = tid & 63, og = tid >> 6;
    float o[32] = {};
    for (int k4 = 0; k4 < 32; k4++) {
        float w0 = W_qz[(k4 * 4 + 0) * 64 + oc];
        float w1 = W_qz[(k4 * 4 + 1) * 64 + oc];
        float w2 = W_qz[(k4 * 4 + 2) * 64 + oc];
        float w3 = W_qz[(k4 * 4 + 3) * 64 + oc];
        #pragma unroll
        for (int i = 0; i < 32; i++) {
            float4 h = *(const float4*)&Hs[(og * 32 + i) * 128 + k4 * 4];
            o[i] += h.x * w0 + h.y * w1 + h.z * w2 + h.w * w3;
        }
    }
    const float bq = b_qz[oc];
    #pragma unroll
    for (int i = 0; i < 32; i++)
        out[(size_t)(m0 + og * 32 + i) * 64 + oc] = o[i] + bq;
}

// ---------------- launch ----------------
extern "C" void kernel_launch(void* const* d_in, const int* in_sizes, int n_in,
                              void* d_out, int out_size) {
    const float* inputs = (const float*)d_in[0];
    const float* past   = (const float*)d_in[1];
    const float* W_in   = (const float*)d_in[2];
    const float* b_in   = (const float*)d_in[3];
    const float* W_pos  = (const float*)d_in[4];
    const float* b_pos  = (const float*)d_in[5];
    const float* W_fc2  = (const float*)d_in[6];
    const float* b_fc2  = (const float*)d_in[7];
    const float* W_fc3  = (const float*)d_in[8];
    const float* b_fc3  = (const float*)d_in[9];
    const float* W_msg  = (const float*)d_in[10];
    const float* b_msg  = (const float*)d_in[11];
    const float* W_hyp  = (const float*)d_in[12];
    const float* b_hyp  = (const float*)d_in[13];
    const float* W_line = (const float*)d_in[14];
    const float* W_out  = (const float*)d_in[15];
    const float* b_out  = (const float*)d_in[16];
    const float* W_qz   = (const float*)d_in[17];
    const float* b_qz   = (const float*)d_in[18];
    float* out = (float*)d_out;

    cudaFuncSetAttribute(k_gemm_hyp,   cudaFuncAttributeMaxDynamicSharedMemorySize, HYP_SMEM);
    cudaFuncSetAttribute(k_gemm_final, cudaFuncAttributeMaxDynamicSharedMemorySize, FIN_SMEM);

    pk1<<<1, 256>>>(W_in, b_in, W_pos, b_pos);
    pk2<<<12, 256>>>(W_fc2);
    pk3a<<<1, 256>>>(b_fc2);
    pk3b<<<49, 256>>>(W_fc3, b_fc3);
    scene_kernel<<<B_SZ, 256>>>(inputs);
    k_gemm_msg<<<dim3(2, BN_ROWS / 128), 256>>>(W_msg, b_msg);
    k_gemm_hyp<<<BN_ROWS / 64, 256, HYP_SMEM>>>(W_hyp, b_hyp, W_line);
    k_gemm_final<<<BN_ROWS / 128, 256, FIN_SMEM>>>(past, W_out, b_out, W_qz, b_qz, out);
}

// round 2
// speedup vs baseline: 1.0011x; 1.0011x over previous
#include <cuda_runtime.h>
#include <math.h>

// Problem constants
#define B_SZ   4096
#define N_AG   11
#define L_T    12
#define D_DIM  256
#define BN_ROWS (B_SZ * N_AG)      // 45056

// ---------------- packed f32x2 helpers ----------------
__device__ __forceinline__ unsigned long long dupf(float x) {
    unsigned long long r;
    asm("mov.b64 %0, {%1, %1};" : "=l"(r) : "f"(x));
    return r;
}
__device__ __forceinline__ void ffma2(unsigned long long& d,
                                      unsigned long long a, unsigned long long b) {
    asm("fma.rn.f32x2 %0, %1, %2, %0;" : "+l"(d) : "l"(a), "l"(b));
}
__device__ __forceinline__ float2 unpk(unsigned long long v) {
    float2 r;
    asm("mov.b64 {%0, %1}, %2;" : "=f"(r.x), "=f"(r.y) : "l"(v));
    return r;
}

// ---------------- device scratch (no dynamic allocation allowed) ----------------
__device__ float g_M4[4 * 256];          // W_in @ W_pos[:256]
__device__ float g_biasT[12 * 256];      // per-timestep bias after W_pos
__device__ float g_Weff[48 * 256];       // folded input->fc2
__device__ float g_ceffp[12 * 256];      // partial const vectors
__device__ float g_ceff[256];
__device__ float g_G[48 * 256];          // folded input->ftraj matrix
__device__ float g_cb[11 * 256];         // per-agent bias (incl. eye@W_fc3)
__device__ float g_msgin[(size_t)BN_ROWS * 512];  // [ftraj | agg]
__device__ float g_hypin[(size_t)BN_ROWS * 512];  // [ftraj | hag]
__device__ float g_inter[(size_t)BN_ROWS * 256];  // ftraj_inter
__device__ float g_feat[(size_t)BN_ROWS * 64];    // feat_bs

// ---------------- precompute kernels (tiny, run every launch) ----------------
__global__ void pk1(const float* __restrict__ W_in, const float* __restrict__ b_in,
                    const float* __restrict__ W_pos, const float* __restrict__ b_pos) {
    __shared__ float pe[12 * 256];
    const int tid = threadIdx.x;   // 256 threads
    for (int idx = tid; idx < 12 * 256; idx += 256) {
        int t = idx >> 8, k = idx & 255;
        int i2 = k & ~1;
        float div = expf(-logf(10000.0f) * (float)i2 / 256.0f);
        float arg = (float)t * div;
        pe[idx] = (k & 1) ? cosf(arg) : sinf(arg);
    }
    __syncthreads();
    const int d = tid;
    float m[4] = {0.f, 0.f, 0.f, 0.f};
    float bb = 0.f;
    for (int k = 0; k < 256; k++) {
        float w = W_pos[k * 256 + d];
        #pragma unroll
        for (int r = 0; r < 4; r++) m[r] += W_in[r * 256 + k] * w;
        bb += b_in[k] * w;
    }
    #pragma unroll
    for (int r = 0; r < 4; r++) g_M4[r * 256 + d] = m[r];
    float acc[12];
    #pragma unroll
    for (int t = 0; t < 12; t++) acc[t] = bb + b_pos[d];
    for (int k = 0; k < 256; k++) {
        float w = W_pos[(256 + k) * 256 + d];
        #pragma unroll
        for (int t = 0; t < 12; t++) acc[t] += pe[t * 256 + k] * w;
    }
    #pragma unroll
    for (int t = 0; t < 12; t++) g_biasT[t * 256 + d] = acc[t];
}

__global__ void pk2(const float* __restrict__ W_fc2) {
    const int t = blockIdx.x, d = threadIdx.x;  // 12 blocks x 256
    float accW[4] = {0.f, 0.f, 0.f, 0.f};
    float accC = 0.f;
    #pragma unroll 4
    for (int m = 0; m < 256; m++) {
        float w = W_fc2[(size_t)((t << 8) + m) * 256 + d];
        float bt = g_biasT[(t << 8) + m];
        #pragma unroll
        for (int r = 0; r < 4; r++) accW[r] += g_M4[r * 256 + m] * w;
        accC += bt * w;
    }
    #pragma unroll
    for (int r = 0; r < 4; r++) g_Weff[(t * 4 + r) * 256 + d] = accW[r];
    g_ceffp[t * 256 + d] = accC;
}

__global__ void pk3a(const float* __restrict__ b_fc2) {
    const int m = threadIdx.x;
    float s = b_fc2[m];
    #pragma unroll
    for (int t = 0; t < 12; t++) s += g_ceffp[t * 256 + m];
    g_ceff[m] = s;
}

__global__ void pk3b(const float* __restrict__ W_fc3, const float* __restrict__ b_fc3) {
    const int d = threadIdx.x;   // 49 blocks x 256
    if (blockIdx.x < 48) {
        const int i = blockIdx.x;
        float a0 = 0.f, a1 = 0.f, a2 = 0.f, a3 = 0.f;
        #pragma unroll 4
        for (int m = 0; m < 256; m += 4) {
            a0 += g_Weff[i * 256 + m + 0] * W_fc3[(m + 0) * 256 + d];
            a1 += g_Weff[i * 256 + m + 1] * W_fc3[(m + 1) * 256 + d];
            a2 += g_Weff[i * 256 + m + 2] * W_fc3[(m + 2) * 256 + d];
            a3 += g_Weff[i * 256 + m + 3] * W_fc3[(m + 3) * 256 + d];
        }
        g_G[i * 256 + d] = (a0 + a1) + (a2 + a3);
    } else {
        float a0 = b_fc3[d], a1 = 0.f, a2 = 0.f, a3 = 0.f;
        #pragma unroll 4
        for (int m = 0; m < 256; m += 4) {
            a0 += g_ceff[m + 0] * W_fc3[(m + 0) * 256 + d];
            a1 += g_ceff[m + 1] * W_fc3[(m + 1) * 256 + d];
            a2 += g_ceff[m + 2] * W_fc3[(m + 2) * 256 + d];
            a3 += g_ceff[m + 3] * W_fc3[(m + 3) * 256 + d];
        }
        float acc = (a0 + a1) + (a2 + a3);
        #pragma unroll
        for (int n = 0; n < 11; n++) g_cb[n * 256 + d] = acc + W_fc3[(256 + n) * 256 + d];
    }
}

// ---------------- per-scene kernel: ftraj, corr/threshold, attn, agg, hag ----------------
__global__ void __launch_bounds__(256)
scene_kernel(const float* __restrict__ inputs) {
    __shared__ float in_s[11 * 48];
    __shared__ float ft[11 * 256];
    __shared__ float dot_s[121];
    __shared__ float corr_s[121];
    __shared__ float attn_s[121];
    __shared__ float arow_s[121];
    __shared__ float nrm[11];
    __shared__ float thr_s;

    const int b = blockIdx.x, tid = threadIdx.x;
    const float* ip = inputs + (size_t)b * 11 * 48;
    for (int i = tid; i < 528; i += 256) in_s[i] = ip[i];
    __syncthreads();

    float acc[11];
    #pragma unroll
    for (int n = 0; n < 11; n++) acc[n] = g_cb[n * 256 + tid];
    for (int k = 0; k < 48; k++) {
        float g = g_G[k * 256 + tid];
        #pragma unroll
        for (int n = 0; n < 11; n++) acc[n] += in_s[n * 48 + k] * g;
    }
    const size_t rowbase = (size_t)b * 11;
    #pragma unroll
    for (int n = 0; n < 11; n++) {
        ft[n * 256 + tid] = acc[n];
        g_msgin[(rowbase + n) * 512 + tid] = acc[n];
        g_hypin[(rowbase + n) * 512 + tid] = acc[n];
    }
    __syncthreads();

    const int warp = tid >> 5, lane = tid & 31;
    for (int p = warp; p < 121; p += 8) {
        int n = p / 11, m = p % 11;
        if (m < n) continue;
        float s = 0.f;
        #pragma unroll
        for (int i = 0; i < 8; i++)
            s += ft[n * 256 + lane + 32 * i] * ft[m * 256 + lane + 32 * i];
        #pragma unroll
        for (int o = 16; o > 0; o >>= 1) s += __shfl_down_sync(0xffffffffu, s, o);
        if (lane == 0) { dot_s[n * 11 + m] = s; dot_s[m * 11 + n] = s; }
    }
    __syncthreads();
    if (tid < 11) nrm[tid] = sqrtf(dot_s[tid * 11 + tid]);
    __syncthreads();
    if (tid < 121) {
        int n = tid / 11, m = tid % 11;
        corr_s[tid] = dot_s[tid] / (nrm[n] * nrm[m]);
    }
    __syncthreads();
    if (tid == 0) {
        float a = corr_s[0];
        for (int i = 1; i < 121; i++) a = fminf(a, corr_s[i]);
        float thr;
        if (a < 0.4f)                         thr = 0.4f;
        else if (a > 0.4f && a < 0.6f)        thr = a + 0.1f;
        else                                  thr = a + 0.03f;
        thr_s = thr;
    }
    __syncthreads();
    if (tid < 11) {
        const int n = tid;
        const float thr = thr_s;
        float rs = 0.f;
        #pragma unroll
        for (int m = 0; m < 11; m++) rs += (corr_s[n * 11 + m] >= thr) ? 1.0f : 0.0f;
        const float inv = 1.0f / fmaxf(rs, 1.0f);
        #pragma unroll
        for (int m = 0; m < 11; m++)
            arow_s[n * 11 + m] = (corr_s[n * 11 + m] >= thr) ? inv : 0.0f;
        const float sc = 0.0625f;
        float mx = -1e30f;
        #pragma unroll
        for (int m = 0; m < 11; m++) mx = fmaxf(mx, dot_s[n * 11 + m] * sc);
        float e[11], se = 0.f;
        #pragma unroll
        for (int m = 0; m < 11; m++) { e[m] = expf(dot_s[n * 11 + m] * sc - mx); se += e[m]; }
        const float is = 1.0f / se;
        #pragma unroll
        for (int m = 0; m < 11; m++) attn_s[n * 11 + m] = e[m] * is;
    }
    __syncthreads();
    #pragma unroll
    for (int n = 0; n < 11; n++) {
        float a = 0.f, h = 0.f;
        #pragma unroll
        for (int m = 0; m < 11; m++) {
            float f = ft[m * 256 + tid];
            a += attn_s[n * 11 + m] * f;
            h += arow_s[n * 11 + m] * f;
        }
        g_msgin[(rowbase + n) * 512 + 256 + tid] = a;
        g_hypin[(rowbase + n) * 512 + 256 + tid] = h;
    }
}

// ---------------- GEMM 1: inter = relu(msgin @ W_msg + b_msg)  [45056,512]x[512,256] ----------------
__global__ void __launch_bounds__(256)
k_gemm_msg(const float* __restrict__ W, const float* __restrict__ bias) {
    __shared__ float As[2][8][128];
    __shared__ float Bs[2][8][128];
    const int tid = threadIdx.x;
    const int m0 = blockIdx.y * 128;
    const int n0 = blockIdx.x * 128;
    const int arow = tid >> 1, ac4 = (tid & 1) << 2;
    const int brow = tid >> 5, bc4 = (tid & 31) << 2;
    const float* Ap = g_msgin + (size_t)(m0 + arow) * 512 + ac4;
    const float* Wp = W + (size_t)brow * 256 + n0 + bc4;

    float4 ra = *(const float4*)Ap;
    float4 rb = *(const float4*)Wp;
    As[0][ac4 + 0][arow] = ra.x; As[0][ac4 + 1][arow] = ra.y;
    As[0][ac4 + 2][arow] = ra.z; As[0][ac4 + 3][arow] = ra.w;
    *(float4*)&Bs[0][brow][bc4] = rb;
    __syncthreads();

    unsigned long long acc2[8][4] = {};
    const int ty = tid >> 4, tx = tid & 15;
    #pragma unroll 2
    for (int kt = 0; kt < 64; kt++) {
        const int cur = kt & 1;
        if (kt < 63) {
            ra = *(const float4*)(Ap + (kt + 1) * 8);
            rb = *(const float4*)(Wp + (size_t)(kt + 1) * 2048);
        }
        #pragma unroll
        for (int k = 0; k < 8; k++) {
            float a[8];
            *(float4*)&a[0] = *(const float4*)&As[cur][k][ty * 8];
            *(float4*)&a[4] = *(const float4*)&As[cur][k][ty * 8 + 4];
            ulonglong2 b01 = *(const ulonglong2*)&Bs[cur][k][tx * 8];
            ulonglong2 b23 = *(const ulonglong2*)&Bs[cur][k][tx * 8 + 4];
            #pragma unroll
            for (int i = 0; i < 8; i++) {
                unsigned long long ap = dupf(a[i]);
                ffma2(acc2[i][0], ap, b01.x);
                ffma2(acc2[i][1], ap, b01.y);
                ffma2(acc2[i][2], ap, b23.x);
                ffma2(acc2[i][3], ap, b23.y);
            }
        }
        if (kt < 63) {
            const int nxt = cur ^ 1;
            As[nxt][ac4 + 0][arow] = ra.x; As[nxt][ac4 + 1][arow] = ra.y;
            As[nxt][ac4 + 2][arow] = ra.z; As[nxt][ac4 + 3][arow] = ra.w;
            *(float4*)&Bs[nxt][brow][bc4] = rb;
            __syncthreads();
        }
    }
    float bn[8];
    #pragma unroll
    for (int j = 0; j < 8; j++) bn[j] = bias[n0 + tx * 8 + j];
    #pragma unroll
    for (int i = 0; i < 8; i++) {
        float o[8];
        #pragma unroll
        for (int j2 = 0; j2 < 4; j2++) {
            float2 v = unpk(acc2[i][j2]);
            o[j2 * 2 + 0] = fmaxf(v.x + bn[j2 * 2 + 0], 0.f);
            o[j2 * 2 + 1] = fmaxf(v.y + bn[j2 * 2 + 1], 0.f);
        }
        float* cp = g_inter + (size_t)(m0 + ty * 8 + i) * 256 + n0 + tx * 8;
        *(float4*)cp = *(float4*)&o[0];
        *(float4*)(cp + 4) = *(float4*)&o[4];
    }
}

// ---------------- GEMM 2: hyp = relu(hypin @ W_hyp + b_hyp); feat = hyp @ W_line (fused) ----------------
#define HYP_SMEM ((2*8*64 + 2*8*256 + 64*256) * 4)
__global__ void __launch_bounds__(256)
k_gemm_hyp(const float* __restrict__ W, const float* __restrict__ bias,
           const float* __restrict__ W_line) {
    extern __shared__ float sm[];
    float* As = sm;               // [2][8][64]
    float* Bs = sm + 1024;        // [2][8][256]
    float* Hs = sm + 1024 + 4096; // [64][256]
    const int tid = threadIdx.x;
    const int m0 = blockIdx.x * 64;
    const int arow = tid >> 1, ac4 = (tid & 1) << 2;
    const int f0r = tid >> 6, f0c = (tid & 63) << 2;
    const int f1r = 4 + (tid >> 6);
    const float* Ap = g_hypin + (size_t)(m0 + arow) * 512 + ac4;

    float4 ra = make_float4(0.f, 0.f, 0.f, 0.f), rb0, rb1;
    if (tid < 128) ra = *(const float4*)Ap;
    rb0 = *(const float4*)(W + (size_t)f0r * 256 + f0c);
    rb1 = *(const float4*)(W + (size_t)f1r * 256 + f0c);
    if (tid < 128) {
        As[(ac4 + 0) * 64 + arow] = ra.x; As[(ac4 + 1) * 64 + arow] = ra.y;
        As[(ac4 + 2) * 64 + arow] = ra.z; As[(ac4 + 3) * 64 + arow] = ra.w;
    }
    *(float4*)&Bs[f0r * 256 + f0c] = rb0;
    *(float4*)&Bs[f1r * 256 + f0c] = rb1;
    __syncthreads();

    unsigned long long acc2[8][4] = {};
    const int ty = tid >> 5, tx = tid & 31;
    #pragma unroll 2
    for (int kt = 0; kt < 64; kt++) {
        const int cur = kt & 1;
        if (kt < 63) {
            if (tid < 128) ra = *(const float4*)(Ap + (kt + 1) * 8);
            rb0 = *(const float4*)(W + (size_t)((kt + 1) * 8 + f0r) * 256 + f0c);
            rb1 = *(const float4*)(W + (size_t)((kt + 1) * 8 + f1r) * 256 + f0c);
        }
        const float* Asc = As + cur * 512;
        const float* Bsc = Bs + cur * 2048;
        #pragma unroll
        for (int k = 0; k < 8; k++) {
            float a[8];
            *(float4*)&a[0] = *(const float4*)&Asc[k * 64 + ty * 8];
            *(float4*)&a[4] = *(const float4*)&Asc[k * 64 + ty * 8 + 4];
            ulonglong2 b01 = *(const ulonglong2*)&Bsc[k * 256 + tx * 8];
            ulonglong2 b23 = *(const ulonglong2*)&Bsc[k * 256 + tx * 8 + 4];
            #pragma unroll
            for (int i = 0; i < 8; i++) {
                unsigned long long ap = dupf(a[i]);
                ffma2(acc2[i][0], ap, b01.x);
                ffma2(acc2[i][1], ap, b01.y);
                ffma2(acc2[i][2], ap, b23.x);
                ffma2(acc2[i][3], ap, b23.y);
            }
        }
        if (kt < 63) {
            const int nxt = cur ^ 1;
            if (tid < 128) {
                As[nxt * 512 + (ac4 + 0) * 64 + arow] = ra.x;
                As[nxt * 512 + (ac4 + 1) * 64 + arow] = ra.y;
                As[nxt * 512 + (ac4 + 2) * 64 + arow] = ra.z;
                As[nxt * 512 + (ac4 + 3) * 64 + arow] = ra.w;
            }
            *(float4*)&Bs[nxt * 2048 + f0r * 256 + f0c] = rb0;
            *(float4*)&Bs[nxt * 2048 + f1r * 256 + f0c] = rb1;
            __syncthreads();
        }
    }
    // epilogue 1: hyp -> smem (never hits HBM)
    #pragma unroll
    for (int j2 = 0; j2 < 4; j2++) {
        float b0 = bias[tx * 8 + j2 * 2 + 0];
        float b1 = bias[tx * 8 + j2 * 2 + 1];
        #pragma unroll
        for (int i = 0; i < 8; i++) {
            float2 v = unpk(acc2[i][j2]);
            Hs[(ty * 8 + i) * 256 + tx * 8 + j2 * 2 + 0] = fmaxf(v.x + b0, 0.f);
            Hs[(ty * 8 + i) * 256 + tx * 8 + j2 * 2 + 1] = fmaxf(v.y + b1, 0.f);
        }
    }
    __syncthreads();
    // epilogue 2: feat = Hs @ W_line  (64x256 @ 256x64)
    const int oc = tid & 63, og = tid >> 6;
    float o[16] = {};
    for (int k4 = 0; k4 < 64; k4++) {
        float w0 = W_line[(k4 * 4 + 0) * 64 + oc];
        float w1 = W_line[(k4 * 4 + 1) * 64 + oc];
        float w2 = W_line[(k4 * 4 + 2) * 64 + oc];
        float w3 = W_line[(k4 * 4 + 3) * 64 + oc];
        #pragma unroll
        for (int i = 0; i < 16; i++) {
            float4 h = *(const float4*)&Hs[(og * 16 + i) * 256 + k4 * 4];
            o[i] += h.x * w0 + h.y * w1 + h.z * w2 + h.w * w3;
        }
    }
    #pragma unroll
    for (int i = 0; i < 16; i++)
        g_feat[(size_t)(m0 + og * 16 + i) * 64 + oc] = o[i];
}

// ---------------- GEMM 3: h = relu([past|ftraj|inter|feat] @ W_out + b_out); out = h @ W_qz + b_qz ----------------
#define FIN_SMEM ((2048 + 2048 + 128*128) * 4)
__global__ void __launch_bounds__(256)
k_gemm_final(const float* __restrict__ past,
             const float* __restrict__ W_out, const float* __restrict__ b_out,
             const float* __restrict__ W_qz,  const float* __restrict__ b_qz,
             float* __restrict__ out) {
    extern __shared__ float sm[];
    float* As = sm;          // [2][8][128]
    float* Bs = sm + 2048;   // [2][8][128]
    float* Hs = sm + 4096;   // [128][128]
    const int tid = threadIdx.x;
    const int m0 = blockIdx.x * 128;
    const int arow = tid >> 1, ac4 = (tid & 1) << 2;
    const int brow = tid >> 5, bc4 = (tid & 31) << 2;
    const size_t grow = (size_t)(m0 + arow);

    auto aload = [&](int kt) -> float4 {
        const int k0 = kt * 8 + ac4;
        const float* p;
        if (k0 < 960)        p = past    + grow * 960 + k0;
        else if (k0 < 1216)  p = g_msgin + grow * 512 + (k0 - 960);
        else if (k0 < 1472)  p = g_inter + grow * 256 + (k0 - 1216);
        else                 p = g_feat  + grow * 64  + (k0 - 1472);
        return *(const float4*)p;
    };

    float4 ra = aload(0);
    float4 rb = *(const float4*)(W_out + (size_t)brow * 128 + bc4);
    As[(ac4 + 0) * 128 + arow] = ra.x; As[(ac4 + 1) * 128 + arow] = ra.y;
    As[(ac4 + 2) * 128 + arow] = ra.z; As[(ac4 + 3) * 128 + arow] = ra.w;
    *(float4*)&Bs[brow * 128 + bc4] = rb;
    __syncthreads();

    unsigned long long acc2[8][4] = {};
    const int ty = tid >> 4, tx = tid & 15;
    #pragma unroll 2
    for (int kt = 0; kt < 192; kt++) {
        const int cur = kt & 1;
        if (kt < 191) {
            ra = aload(kt + 1);
            rb = *(const float4*)(W_out + (size_t)((kt + 1) * 8 + brow) * 128 + bc4);
        }
        const float* Asc = As + cur * 1024;
        const float* Bsc = Bs + cur * 1024;
        #pragma unroll
        for (int k = 0; k < 8; k++) {
            float a[8];
            *(float4*)&a[0] = *(const float4*)&Asc[k * 128 + ty * 8];
            *(float4*)&a[4] = *(const float4*)&Asc[k * 128 + ty * 8 + 4];
            ulonglong2 b01 = *(const ulonglong2*)&Bsc[k * 128 + tx * 8];
            ulonglong2 b23 = *(const ulonglong2*)&Bsc[k * 128 + tx * 8 + 4];
            #pragma unroll
            for (int i = 0; i < 8; i++) {
                unsigned long long ap = dupf(a[i]);
                ffma2(acc2[i][0], ap, b01.x);
                ffma2(acc2[i][1], ap, b01.y);
                ffma2(acc2[i][2], ap, b23.x);
                ffma2(acc2[i][3], ap, b23.y);
            }
        }
        if (kt < 191) {
            const int nxt = cur ^ 1;
            As[nxt * 1024 + (ac4 + 0) * 128 + arow] = ra.x;
            As[nxt * 1024 + (ac4 + 1) * 128 + arow] = ra.y;
            As[nxt * 1024 + (ac4 + 2) * 128 + arow] = ra.z;
            As[nxt * 1024 + (ac4 + 3) * 128 + arow] = ra.w;
            *(float4*)&Bs[nxt * 1024 + brow * 128 + bc4] = rb;
            __syncthreads();
        }
    }
    // epilogue 1: h = relu(acc + b_out) -> Hs
    #pragma unroll
    for (int j2 = 0; j2 < 4; j2++) {
        float b0 = b_out[tx * 8 + j2 * 2 + 0];
        float b1 = b_out[tx * 8 + j2 * 2 + 1];
        #pragma unroll
        for (int i = 0; i < 8; i++) {
            float2 v = unpk(acc2[i][j2]);
            Hs[(ty * 8 + i) * 128 + tx * 8 + j2 * 2 + 0] = fmaxf(v.x + b0, 0.f);
            Hs[(ty * 8 + i) * 128 + tx * 8 + j2 * 2 + 1] = fmaxf(v.y + b1, 0.f);
        }
    }
    __syncthreads();
    // epilogue 2: out = Hs @ W_qz + b_qz  (128x128 @ 128x64)
    const int oc = tid & 63, og = tid >> 6;
    float o[32] = {};
    for (int k4 = 0; k4 < 32; k4++) {
        float w0 = W_qz[(k4 * 4 + 0) * 64 + oc];
        float w1 = W_qz[(k4 * 4 + 1) * 64 + oc];
        float w2 = W_qz[(k4 * 4 + 2) * 64 + oc];
        float w3 = W_qz[(k4 * 4 + 3) * 64 + oc];
        #pragma unroll
        for (int i = 0; i < 32; i++) {
            float4 h = *(const float4*)&Hs[(og * 32 + i) * 128 + k4 * 4];
            o[i] += h.x * w0 + h.y * w1 + h.z * w2 + h.w * w3;
        }
    }
    const float bq = b_qz[oc];
    #pragma unroll
    for (int i = 0; i < 32; i++)
        out[(size_t)(m0 + og * 32 + i) * 64 + oc] = o[i] + bq;
}

// ---------------- launch ----------------
extern "C" void kernel_launch(void* const* d_in, const int* in_sizes, int n_in,
                              void* d_out, int out_size) {
    const float* inputs = (const float*)d_in[0];
    const float* past   = (const float*)d_in[1];
    const float* W_in   = (const float*)d_in[2];
    const float* b_in   = (const float*)d_in[3];
    const float* W_pos  = (const float*)d_in[4];
    const float* b_pos  = (const float*)d_in[5];
    const float* W_fc2  = (const float*)d_in[6];
    const float* b_fc2  = (const float*)d_in[7];
    const float* W_fc3  = (const float*)d_in[8];
    const float* b_fc3  = (const float*)d_in[9];
    const float* W_msg  = (const float*)d_in[10];
    const float* b_msg  = (const float*)d_in[11];
    const float* W_hyp  = (const float*)d_in[12];
    const float* b_hyp  = (const float*)d_in[13];
    const float* W_line = (const float*)d_in[14];
    const float* W_out  = (const float*)d_in[15];
    const float* b_out  = (const float*)d_in[16];
    const float* W_qz   = (const float*)d_in[17];
    const float* b_qz   = (const float*)d_in[18];
    float* out = (float*)d_out;

    cudaFuncSetAttribute(k_gemm_hyp,   cudaFuncAttributeMaxDynamicSharedMemorySize, HYP_SMEM);
    cudaFuncSetAttribute(k_gemm_final, cudaFuncAttributeMaxDynamicSharedMemorySize, FIN_SMEM);

    pk1<<<1, 256>>>(W_in, b_in, W_pos, b_pos);
    pk2<<<12, 256>>>(W_fc2);
    pk3a<<<1, 256>>>(b_fc2);
    pk3b<<<49, 256>>>(W_fc3, b_fc3);
    scene_kernel<<<B_SZ, 256>>>(inputs);
    k_gemm_msg<<<dim3(2, BN_ROWS / 128), 256>>>(W_msg, b_msg);
    k_gemm_hyp<<<BN_ROWS / 64, 256, HYP_SMEM>>>(W_hyp, b_hyp, W_line);
    k_gemm_final<<<BN_ROWS / 128, 256, FIN_SMEM>>>(past, W_out, b_out, W_qz, b_qz, out);
}